// round 2
// baseline (speedup 1.0000x reference)
#include <cuda_runtime.h>
#include <cstddef>

#define N_NODES 100000
#define N_EDGES 3200000
#define DIM 512

// ---------------- scratch (static device globals; no allocation) -------------
__device__ float g_h0[(size_t)N_NODES * DIM];   // gemm output / layer buffer
__device__ float g_h1[(size_t)N_NODES * DIM];   // spmm output buffer
__device__ int   g_counts[N_NODES];
__device__ int   g_row_ptr[N_NODES + 1];
__device__ int   g_cursor[N_NODES];
__device__ int   g_esrc[N_EDGES];
__device__ float g_eval[N_EDGES];

// ---------------- CSR build ---------------------------------------------------
__global__ void zero_counts_kernel() {
    int i = blockIdx.x * blockDim.x + threadIdx.x;
    if (i < N_NODES) g_counts[i] = 0;
}

__global__ void count_kernel(const int* __restrict__ dst) {
    int e = blockIdx.x * blockDim.x + threadIdx.x;
    if (e < N_EDGES) atomicAdd(&g_counts[dst[e]], 1);
}

// single-block exclusive scan of g_counts -> g_row_ptr (n = N_NODES)
__global__ void scan_kernel() {
    __shared__ int ssum[1024];
    const int n = N_NODES;
    int tid = threadIdx.x;
    int chunk = (n + 1023) / 1024;
    int start = tid * chunk;
    int end = start + chunk; if (end > n) end = n; if (start > n) start = n;

    int s = 0;
    for (int i = start; i < end; i++) s += g_counts[i];
    ssum[tid] = s;
    __syncthreads();
    // inclusive Hillis-Steele scan over 1024 partials
    for (int off = 1; off < 1024; off <<= 1) {
        int v = 0;
        if (tid >= off) v = ssum[tid - off];
        __syncthreads();
        ssum[tid] += v;
        __syncthreads();
    }
    int run = (tid == 0) ? 0 : ssum[tid - 1];
    for (int i = start; i < end; i++) {
        g_row_ptr[i] = run;
        run += g_counts[i];
    }
    if (tid == 1023) g_row_ptr[n] = ssum[1023];
}

__global__ void copy_cursor_kernel() {
    int i = blockIdx.x * blockDim.x + threadIdx.x;
    if (i < N_NODES) g_cursor[i] = g_row_ptr[i];
}

__global__ void scatter_kernel(const int* __restrict__ src,
                               const int* __restrict__ dst,
                               const float* __restrict__ val) {
    int e = blockIdx.x * blockDim.x + threadIdx.x;
    if (e < N_EDGES) {
        int d = dst[e];
        int pos = atomicAdd(&g_cursor[d], 1);
        g_esrc[pos] = src[e];
        g_eval[pos] = val[e];
    }
}

// ---------------- SGEMM + bias:  C[M,512] = A[M,512] @ B[512,512] + bias -----
#define BM 128
#define BN 128
#define BK 8
#define TM 8
#define TN 8

__global__ __launch_bounds__(256, 2)
void sgemm_bias_kernel(const float* __restrict__ A, const float* __restrict__ B,
                       const float* __restrict__ bias, float* __restrict__ C, int M) {
    const int N = DIM, K = DIM;
    __shared__ float As[BK][BM];
    __shared__ float Bs[BK][BN];

    int tid = threadIdx.x;
    int bRow = blockIdx.y * BM;
    int bCol = blockIdx.x * BN;

    int tx = tid & 15;        // 0..15 (cols)
    int ty = tid >> 4;        // 0..15 (rows)

    // A tile load mapping: thread -> (row in tile, which half of 8 k's)
    int ar = tid >> 1;        // 0..127
    int ah = tid & 1;         // 0..1
    // B tile load mapping
    int bkk = tid >> 5;       // 0..7  (k within tile)
    int bc  = (tid & 31) << 2; // 0..124 step 4

    float acc[TM][TN];
    #pragma unroll
    for (int i = 0; i < TM; i++)
        #pragma unroll
        for (int j = 0; j < TN; j++) acc[i][j] = 0.0f;

    for (int k0 = 0; k0 < K; k0 += BK) {
        int grow = bRow + ar;
        float4 av = make_float4(0.f, 0.f, 0.f, 0.f);
        if (grow < M)
            av = *(const float4*)(A + (size_t)grow * K + k0 + ah * 4);
        As[ah * 4 + 0][ar] = av.x;
        As[ah * 4 + 1][ar] = av.y;
        As[ah * 4 + 2][ar] = av.z;
        As[ah * 4 + 3][ar] = av.w;

        float4 bv = *(const float4*)(B + (size_t)(k0 + bkk) * N + bCol + bc);
        *(float4*)&Bs[bkk][bc] = bv;

        __syncthreads();

        #pragma unroll
        for (int k = 0; k < BK; k++) {
            float ra[TM], rb[TN];
            #pragma unroll
            for (int i = 0; i < TM; i++) ra[i] = As[k][ty * TM + i];
            #pragma unroll
            for (int j = 0; j < TN; j++) rb[j] = Bs[k][tx * TN + j];
            #pragma unroll
            for (int i = 0; i < TM; i++)
                #pragma unroll
                for (int j = 0; j < TN; j++)
                    acc[i][j] += ra[i] * rb[j];
        }
        __syncthreads();
    }

    // epilogue: add bias, store
    #pragma unroll
    for (int i = 0; i < TM; i++) {
        int grow = bRow + ty * TM + i;
        if (grow < M) {
            float* crow = C + (size_t)grow * N + bCol + tx * TN;
            #pragma unroll
            for (int j = 0; j < TN; j += 4) {
                float4 v;
                v.x = acc[i][j + 0] + bias[bCol + tx * TN + j + 0];
                v.y = acc[i][j + 1] + bias[bCol + tx * TN + j + 1];
                v.z = acc[i][j + 2] + bias[bCol + tx * TN + j + 2];
                v.w = acc[i][j + 3] + bias[bCol + tx * TN + j + 3];
                *(float4*)(crow + j) = v;
            }
        }
    }
}

// ---------------- CSR SpMM + ReLU: out[d] = relu(sum_e val*h[src]) -----------
__global__ __launch_bounds__(128)
void spmm_relu_kernel(const float* __restrict__ h, float* __restrict__ out) {
    int node = blockIdx.x;
    int tid = threadIdx.x;           // 128 threads x float4 = 512 cols
    int beg = g_row_ptr[node];
    int end = g_row_ptr[node + 1];

    float4 acc = make_float4(0.f, 0.f, 0.f, 0.f);
    for (int e = beg; e < end; e++) {
        int   s = g_esrc[e];
        float v = g_eval[e];
        float4 hv = *(const float4*)(h + (size_t)s * DIM + tid * 4);
        acc.x += v * hv.x;
        acc.y += v * hv.y;
        acc.z += v * hv.z;
        acc.w += v * hv.w;
    }
    acc.x = fmaxf(acc.x, 0.f);
    acc.y = fmaxf(acc.y, 0.f);
    acc.z = fmaxf(acc.z, 0.f);
    acc.w = fmaxf(acc.w, 0.f);
    *(float4*)(out + (size_t)node * DIM + tid * 4) = acc;
}

// ---------------- launch ------------------------------------------------------
extern "C" void kernel_launch(void* const* d_in, const int* in_sizes, int n_in,
                              void* d_out, int out_size) {
    const float* x       = (const float*)d_in[0];
    const int*   adj_src = (const int*)  d_in[1];
    const int*   adj_dst = (const int*)  d_in[2];
    const float* adj_val = (const float*)d_in[3];
    const float* W1      = (const float*)d_in[4];
    const float* b1      = (const float*)d_in[5];
    const float* W2      = (const float*)d_in[6];
    const float* b2      = (const float*)d_in[7];
    float* out = (float*)d_out;

    float* h0 = nullptr;
    float* h1 = nullptr;
    cudaGetSymbolAddress((void**)&h0, g_h0);
    cudaGetSymbolAddress((void**)&h1, g_h1);

    // CSR build (by destination)
    zero_counts_kernel<<<(N_NODES + 255) / 256, 256>>>();
    count_kernel<<<(N_EDGES + 255) / 256, 256>>>(adj_dst);
    scan_kernel<<<1, 1024>>>();
    copy_cursor_kernel<<<(N_NODES + 255) / 256, 256>>>();
    scatter_kernel<<<(N_EDGES + 255) / 256, 256>>>(adj_src, adj_dst, adj_val);

    dim3 ggrid(DIM / BN, (N_NODES + BM - 1) / BM);

    // Layer 1: x @ W1 + b1 -> h0 ; spmm+relu -> h1
    sgemm_bias_kernel<<<ggrid, 256>>>(x, W1, b1, h0, N_NODES);
    spmm_relu_kernel<<<N_NODES, 128>>>(h0, h1);

    // Layer 2: h1 @ W2 + b2 -> h0 ; spmm+relu -> out
    sgemm_bias_kernel<<<ggrid, 256>>>(h1, W2, b2, h0, N_NODES);
    spmm_relu_kernel<<<N_NODES, 128>>>(h0, out);
}

// round 4
// speedup vs baseline: 1.5695x; 1.5695x over previous
#include <cuda_runtime.h>
#include <cuda_bf16.h>
#include <cstdint>
#include <cstddef>
#include <cstring>

#define N_NODES 100000
#define N_EDGES 3200000
#define DIM 512

// ---------------- scratch (static device globals; no allocation) -------------
__device__ float g_h0[(size_t)N_NODES * DIM];
__device__ float g_h1[(size_t)N_NODES * DIM];
__device__ float g_Wt1[DIM * DIM];
__device__ float g_Wt2[DIM * DIM];
__device__ int   g_counts[N_NODES];
__device__ int   g_row_ptr[N_NODES + 1];
__device__ int   g_cursor[N_NODES];
__device__ int2  g_edge[N_EDGES];      // (src, bitcast val)

// ================= CSR build =================================================
__global__ void zero_counts_kernel() {
    int i = blockIdx.x * blockDim.x + threadIdx.x;
    if (i < N_NODES) g_counts[i] = 0;
}

__global__ void count_kernel(const int* __restrict__ dst) {
    int e = blockIdx.x * blockDim.x + threadIdx.x;
    if (e < N_EDGES) atomicAdd(&g_counts[dst[e]], 1);
}

// single-block exclusive scan: counts -> row_ptr (+cursor init)
__global__ void scan_kernel() {
    __shared__ int ssum[1024];
    const int n = N_NODES;
    int tid = threadIdx.x;
    int chunk = (n + 1023) / 1024;
    int start = tid * chunk;
    int end = start + chunk; if (end > n) end = n; if (start > n) start = n;

    int s = 0;
    for (int i = start; i < end; i++) s += g_counts[i];
    ssum[tid] = s;
    __syncthreads();
    for (int off = 1; off < 1024; off <<= 1) {
        int v = 0;
        if (tid >= off) v = ssum[tid - off];
        __syncthreads();
        ssum[tid] += v;
        __syncthreads();
    }
    int run = (tid == 0) ? 0 : ssum[tid - 1];
    for (int i = start; i < end; i++) {
        g_row_ptr[i] = run;
        g_cursor[i] = run;
        run += g_counts[i];
    }
    if (tid == 1023) g_row_ptr[n] = ssum[1023];
}

__global__ void scatter_kernel(const int* __restrict__ src,
                               const int* __restrict__ dst,
                               const float* __restrict__ val) {
    int e = blockIdx.x * blockDim.x + threadIdx.x;
    if (e < N_EDGES) {
        int d = dst[e];
        int pos = atomicAdd(&g_cursor[d], 1);
        g_edge[pos] = make_int2(src[e], __float_as_int(val[e]));
    }
}

// ================= W transpose: Wt[n*512+k] = W[k*512+n] =====================
__global__ void transpose512(const float* __restrict__ W, float* __restrict__ Wt) {
    __shared__ float t[32][33];
    int bx = blockIdx.x * 32, by = blockIdx.y * 32;
    t[threadIdx.y][threadIdx.x] = W[(by + threadIdx.y) * DIM + bx + threadIdx.x];
    __syncthreads();
    Wt[(bx + threadIdx.y) * DIM + by + threadIdx.x] = t[threadIdx.x][threadIdx.y];
}

// ================= split-bf16 tensor-core GEMM ===============================
// C[M,512] = A[M,512] @ W + bias, with Wt = W^T stored [N][K] (k-contiguous).
// x = hi + lo (both bf16); C = AH*BH + AH*BL + AL*BH  (error ~2^-18).
// mma.sync.aligned.m16n8k16.row.col.f32.bf16.bf16.f32 (legacy HMMA path,
// valid on plain compute_103 — tcgen05 is NOT available in this build).

#define BM 128
#define BN 128
#define BKT 16                 // k per stage
#define NSTG (DIM / BKT)       // 32 stages
#define RSW 12                 // smem row stride in 32-bit words (24 bf16)

__device__ __forceinline__ uint32_t pack_bf2(__nv_bfloat16 a, __nv_bfloat16 b) {
    __nv_bfloat162 t(a, b);   // .x = a (low half), .y = b (high half)
    uint32_t p;
    memcpy(&p, &t, 4);
    return p;
}

// convert float4 (4 consecutive k) -> 2 hi words + 2 lo words
__device__ __forceinline__ void cvt_split4(float4 v, uint32_t* hi, uint32_t* lo) {
    __nv_bfloat16 hx = __float2bfloat16(v.x);
    __nv_bfloat16 hy = __float2bfloat16(v.y);
    __nv_bfloat16 hz = __float2bfloat16(v.z);
    __nv_bfloat16 hw = __float2bfloat16(v.w);
    float rx = v.x - __bfloat162float(hx);
    float ry = v.y - __bfloat162float(hy);
    float rz = v.z - __bfloat162float(hz);
    float rw = v.w - __bfloat162float(hw);
    hi[0] = pack_bf2(hx, hy);
    hi[1] = pack_bf2(hz, hw);
    lo[0] = pack_bf2(__float2bfloat16(rx), __float2bfloat16(ry));
    lo[1] = pack_bf2(__float2bfloat16(rz), __float2bfloat16(rw));
}

__device__ __forceinline__ void mma_bf16(float* c, const uint32_t* a, const uint32_t* b) {
    asm volatile(
        "mma.sync.aligned.m16n8k16.row.col.f32.bf16.bf16.f32 "
        "{%0,%1,%2,%3}, {%4,%5,%6,%7}, {%8,%9}, {%0,%1,%2,%3};\n"
        : "+f"(c[0]), "+f"(c[1]), "+f"(c[2]), "+f"(c[3])
        : "r"(a[0]), "r"(a[1]), "r"(a[2]), "r"(a[3]), "r"(b[0]), "r"(b[1]));
}

__global__ void __launch_bounds__(256, 2)
gemm_tc_kernel(const float* __restrict__ A, const float* __restrict__ Wt,
               const float* __restrict__ bias, float* __restrict__ C, int M) {
    __shared__ uint32_t sAH[BM * RSW];
    __shared__ uint32_t sAL[BM * RSW];
    __shared__ uint32_t sBH[BN * RSW];
    __shared__ uint32_t sBL[BN * RSW];

    const int tid = threadIdx.x;
    const int wid = tid >> 5;
    const int lane = tid & 31;
    const int lq = lane >> 2;        // 0..7
    const int k0w = lane & 3;        // k-pair word index 0..3
    const int bRow = blockIdx.y * BM;
    const int bCol = blockIdx.x * BN;
    const int warp_m = (wid >> 2) * 64;   // 0 or 64
    const int warp_n = (wid & 3) * 32;    // 0,32,64,96

    // global load mapping: row = tid/2 (0..127), quad = tid&1 (k half 0..1)
    const int grow_l = tid >> 1;
    const int quad = tid & 1;
    const int arow = bRow + grow_l;
    const bool a_ok = arow < M;
    const float* Ap = A + (size_t)arow * DIM + quad * 8;
    const float* Bp = Wt + (size_t)(bCol + grow_l) * DIM + quad * 8;
    const int sbase = grow_l * RSW + quad * 4;

    float acc[4][4][4];
    #pragma unroll
    for (int i = 0; i < 4; i++)
        #pragma unroll
        for (int j = 0; j < 4; j++)
            #pragma unroll
            for (int q = 0; q < 4; q++) acc[i][j][q] = 0.f;

    float4 va0, va1, vb0, vb1;
    va0 = a_ok ? *(const float4*)(Ap + 0) : make_float4(0,0,0,0);
    va1 = a_ok ? *(const float4*)(Ap + 4) : make_float4(0,0,0,0);
    vb0 = *(const float4*)(Bp + 0);
    vb1 = *(const float4*)(Bp + 4);

    for (int kt = 0; kt < NSTG; kt++) {
        // convert + store current stage
        cvt_split4(va0, &sAH[sbase + 0], &sAL[sbase + 0]);
        cvt_split4(va1, &sAH[sbase + 2], &sAL[sbase + 2]);
        cvt_split4(vb0, &sBH[sbase + 0], &sBL[sbase + 0]);
        cvt_split4(vb1, &sBH[sbase + 2], &sBL[sbase + 2]);
        __syncthreads();

        // prefetch next stage
        if (kt + 1 < NSTG) {
            Ap += BKT; Bp += BKT;
            va0 = a_ok ? *(const float4*)(Ap + 0) : make_float4(0,0,0,0);
            va1 = a_ok ? *(const float4*)(Ap + 4) : make_float4(0,0,0,0);
            vb0 = *(const float4*)(Bp + 0);
            vb1 = *(const float4*)(Bp + 4);
        }

        // B fragments for this warp's 4 n-tiles
        uint32_t bH[4][2], bL[4][2];
        #pragma unroll
        for (int nt = 0; nt < 4; nt++) {
            int bn = (warp_n + nt * 8 + lq) * RSW + k0w;
            bH[nt][0] = sBH[bn];     bH[nt][1] = sBH[bn + 4];
            bL[nt][0] = sBL[bn];     bL[nt][1] = sBL[bn + 4];
        }

        #pragma unroll
        for (int mt = 0; mt < 4; mt++) {
            int r0 = (warp_m + mt * 16 + lq) * RSW + k0w;
            int r8 = r0 + 8 * RSW;
            uint32_t aH[4], aL[4];
            aH[0] = sAH[r0];     aH[1] = sAH[r8];
            aH[2] = sAH[r0 + 4]; aH[3] = sAH[r8 + 4];
            aL[0] = sAL[r0];     aL[1] = sAL[r8];
            aL[2] = sAL[r0 + 4]; aL[3] = sAL[r8 + 4];
            #pragma unroll
            for (int nt = 0; nt < 4; nt++) {
                mma_bf16(acc[mt][nt], aH, bH[nt]);
                mma_bf16(acc[mt][nt], aH, bL[nt]);
                mma_bf16(acc[mt][nt], aL, bH[nt]);
            }
        }
        __syncthreads();
    }

    // epilogue: add bias, store
    #pragma unroll
    for (int mt = 0; mt < 4; mt++) {
        int row = bRow + warp_m + mt * 16 + lq;
        #pragma unroll
        for (int nt = 0; nt < 4; nt++) {
            int col = bCol + warp_n + nt * 8 + (lane & 3) * 2;
            float bx = __ldg(bias + col);
            float by = __ldg(bias + col + 1);
            if (row < M) {
                float2 v = make_float2(acc[mt][nt][0] + bx, acc[mt][nt][1] + by);
                *(float2*)(C + (size_t)row * DIM + col) = v;
            }
            if (row + 8 < M) {
                float2 v = make_float2(acc[mt][nt][2] + bx, acc[mt][nt][3] + by);
                *(float2*)(C + (size_t)(row + 8) * DIM + col) = v;
            }
        }
    }
}

// ================= CSR SpMM + ReLU ==========================================
__global__ __launch_bounds__(128)
void spmm_relu_kernel(const float* __restrict__ h, float* __restrict__ out) {
    int node = blockIdx.x;
    int tid = threadIdx.x;
    int beg = g_row_ptr[node];
    int end = g_row_ptr[node + 1];
    const int coff = tid * 4;

    float4 acc = make_float4(0.f, 0.f, 0.f, 0.f);
    int e = beg;
    for (; e + 4 <= end; e += 4) {
        int2 e0 = g_edge[e + 0];
        int2 e1 = g_edge[e + 1];
        int2 e2 = g_edge[e + 2];
        int2 e3 = g_edge[e + 3];
        float4 h0 = *(const float4*)(h + (size_t)e0.x * DIM + coff);
        float4 h1 = *(const float4*)(h + (size_t)e1.x * DIM + coff);
        float4 h2 = *(const float4*)(h + (size_t)e2.x * DIM + coff);
        float4 h3 = *(const float4*)(h + (size_t)e3.x * DIM + coff);
        float v0 = __int_as_float(e0.y), v1 = __int_as_float(e1.y);
        float v2 = __int_as_float(e2.y), v3 = __int_as_float(e3.y);
        acc.x += v0 * h0.x; acc.y += v0 * h0.y; acc.z += v0 * h0.z; acc.w += v0 * h0.w;
        acc.x += v1 * h1.x; acc.y += v1 * h1.y; acc.z += v1 * h1.z; acc.w += v1 * h1.w;
        acc.x += v2 * h2.x; acc.y += v2 * h2.y; acc.z += v2 * h2.z; acc.w += v2 * h2.w;
        acc.x += v3 * h3.x; acc.y += v3 * h3.y; acc.z += v3 * h3.z; acc.w += v3 * h3.w;
    }
    for (; e < end; e++) {
        int2 ed = g_edge[e];
        float v = __int_as_float(ed.y);
        float4 hv = *(const float4*)(h + (size_t)ed.x * DIM + coff);
        acc.x += v * hv.x; acc.y += v * hv.y; acc.z += v * hv.z; acc.w += v * hv.w;
    }
    acc.x = fmaxf(acc.x, 0.f);
    acc.y = fmaxf(acc.y, 0.f);
    acc.z = fmaxf(acc.z, 0.f);
    acc.w = fmaxf(acc.w, 0.f);
    *(float4*)(out + (size_t)node * DIM + coff) = acc;
}

// ================= launch ====================================================
extern "C" void kernel_launch(void* const* d_in, const int* in_sizes, int n_in,
                              void* d_out, int out_size) {
    const float* x       = (const float*)d_in[0];
    const int*   adj_src = (const int*)  d_in[1];
    const int*   adj_dst = (const int*)  d_in[2];
    const float* adj_val = (const float*)d_in[3];
    const float* W1      = (const float*)d_in[4];
    const float* b1      = (const float*)d_in[5];
    const float* W2      = (const float*)d_in[6];
    const float* b2      = (const float*)d_in[7];
    float* out = (float*)d_out;

    float *h0, *h1, *wt1, *wt2;
    cudaGetSymbolAddress((void**)&h0, g_h0);
    cudaGetSymbolAddress((void**)&h1, g_h1);
    cudaGetSymbolAddress((void**)&wt1, g_Wt1);
    cudaGetSymbolAddress((void**)&wt2, g_Wt2);

    // CSR build (by destination)
    zero_counts_kernel<<<(N_NODES + 255) / 256, 256>>>();
    count_kernel<<<(N_EDGES + 255) / 256, 256>>>(adj_dst);
    scan_kernel<<<1, 1024>>>();
    scatter_kernel<<<(N_EDGES + 255) / 256, 256>>>(adj_src, adj_dst, adj_val);

    // weight transposes
    dim3 tgrid(DIM / 32, DIM / 32), tblk(32, 32);
    transpose512<<<tgrid, tblk>>>(W1, wt1);
    transpose512<<<tgrid, tblk>>>(W2, wt2);

    dim3 ggrid(DIM / BN, (N_NODES + BM - 1) / BM);

    // Layer 1
    gemm_tc_kernel<<<ggrid, 256>>>(x, wt1, b1, h0, N_NODES);
    spmm_relu_kernel<<<N_NODES, 128>>>(h0, h1);
    // Layer 2
    gemm_tc_kernel<<<ggrid, 256>>>(h1, wt2, b2, h0, N_NODES);
    spmm_relu_kernel<<<N_NODES, 128>>>(h0, out);
}